// round 16
// baseline (speedup 1.0000x reference)
#include <cuda_runtime.h>
#include <math.h>
#include <stdint.h>

#define NCTA  128
#define TPB   800             // warps 0..23 = dot workers, warp 24 = control
#define HID   1536
#define INSZ  32
#define NOUT  10
#define STOT  2048
#define UPC   12              // hidden units per CTA
#define RPC   48              // gate rows per CTA
#define HV4   (HID / 4)
#define NWEL  (4 * HID * HID)
#define CTRL  24              // control warp id
#define FPAD  8               // flag padding (32B) to spread L2 lines

// ---------------- persistent device state ----------------
__device__ unsigned short g_hi_hh0[NWEL];
__device__ unsigned short g_hi_ih1[NWEL];
__device__ unsigned short g_hi_hh1[NWEL];
__device__ unsigned char  g_mi_hh0[NWEL];
__device__ unsigned char  g_mi_ih1[NWEL];
__device__ unsigned char  g_mi_hh1[NWEL];

__device__ __align__(16) float g_h0[HID];
__device__ __align__(16) float g_h1[HID];
__device__ float    g_logits[2][NOUT];
__device__ uint2    g_keys[STOT];
__device__ unsigned g_flag[NCTA * FPAD];   // per-CTA arrival flags (epoch values)
__device__ unsigned g_gen;                 // release word
__device__ unsigned g_epoch_base;          // persists across launches

// ---------------- flag-based grid barrier (parallel arrival, no atomics) ----------------
__device__ __forceinline__ void grid_barrier(unsigned& epoch, int cta, int tid) {
    __syncthreads();
    ++epoch;
    if (cta == 0) {
        if (tid > 0 && tid < NCTA) {   // CTA0 has no flag of its own
            unsigned v;
            do {
                asm volatile("ld.acquire.gpu.u32 %0,[%1];"
                             : "=r"(v) : "l"(&g_flag[tid * FPAD]));
            } while ((int)(v - epoch) < 0);
        }
        __syncthreads();               // all flags observed -> CTA0 has seen all writes
        if (tid == 0)
            asm volatile("st.release.gpu.u32 [%0],%1;" :: "l"(&g_gen), "r"(epoch));
    } else {
        if (tid == 0) {
            asm volatile("st.release.gpu.u32 [%0],%1;"
                         :: "l"(&g_flag[cta * FPAD]), "r"(epoch));
            unsigned cur;
            do {
                asm volatile("ld.acquire.gpu.u32 %0,[%1];" : "=r"(cur) : "l"(&g_gen));
            } while ((int)(cur - epoch) < 0);
        }
        __syncthreads();
    }
}

// ---------------- JAX threefry2x32 ----------------
__device__ __forceinline__ void tf_round(uint32_t& x0, uint32_t& x1, int r) {
    x0 += x1;
    x1 = (x1 << r) | (x1 >> (32 - r));
    x1 ^= x0;
}
__device__ __forceinline__ uint2 threefry2x32(uint32_t k0, uint32_t k1,
                                              uint32_t x0, uint32_t x1) {
    uint32_t ks2 = k0 ^ k1 ^ 0x1BD11BDAu;
    x0 += k0; x1 += k1;
    tf_round(x0,x1,13); tf_round(x0,x1,15); tf_round(x0,x1,26); tf_round(x0,x1,6);
    x0 += k1; x1 += ks2 + 1u;
    tf_round(x0,x1,17); tf_round(x0,x1,29); tf_round(x0,x1,16); tf_round(x0,x1,24);
    x0 += ks2; x1 += k0 + 2u;
    tf_round(x0,x1,13); tf_round(x0,x1,15); tf_round(x0,x1,26); tf_round(x0,x1,6);
    x0 += k0; x1 += k1 + 3u;
    tf_round(x0,x1,17); tf_round(x0,x1,29); tf_round(x0,x1,16); tf_round(x0,x1,24);
    x0 += k1; x1 += ks2 + 4u;
    tf_round(x0,x1,13); tf_round(x0,x1,15); tf_round(x0,x1,26); tf_round(x0,x1,6);
    x0 += ks2; x1 += k0 + 5u;
    return make_uint2(x0, x1);
}

__device__ __forceinline__ float sigf(float x) { return 1.0f / (1.0f + expf(-x)); }

__device__ __forceinline__ float prmtf(uint32_t a, uint32_t b, uint32_t s) {
    uint32_t r;
    asm("prmt.b32 %0,%1,%2,%3;" : "=r"(r) : "r"(a), "r"(b), "r"(s));
    return __uint_as_float(r);
}

__device__ __forceinline__ float fma8(uint4 H, uint2 M, float4 x0, float4 x1, float acc) {
    acc = fmaf(prmtf(H.x, M.x, 0x1044u), x0.x, acc);
    acc = fmaf(prmtf(H.x, M.x, 0x3255u), x0.y, acc);
    acc = fmaf(prmtf(H.y, M.x, 0x1066u), x0.z, acc);
    acc = fmaf(prmtf(H.y, M.x, 0x3277u), x0.w, acc);
    acc = fmaf(prmtf(H.z, M.y, 0x1044u), x1.x, acc);
    acc = fmaf(prmtf(H.z, M.y, 0x3255u), x1.y, acc);
    acc = fmaf(prmtf(H.w, M.y, 0x1066u), x1.z, acc);
    acc = fmaf(prmtf(H.w, M.y, 0x3277u), x1.w, acc);
    return acc;
}

// half-row dot: 4 consecutive rows, one half, x from SMEM (proven engine)
__device__ __forceinline__ void dotg1(const unsigned short* __restrict__ hi,
                                      const unsigned char*  __restrict__ mi,
                                      size_t rowb,
                                      const float4* __restrict__ sh4,
                                      int xbase, int lane, int half, int rloc,
                                      float* __restrict__ s_d) {
    float a0 = 0.f, a1 = 0.f, a2 = 0.f, a3 = 0.f;
    #pragma unroll
    for (int c = 0; c < 3; ++c) {
        const size_t o = rowb + (size_t)c * 256;
        uint4 H0 = __ldcg((const uint4*)(hi + o));
        uint4 H1 = __ldcg((const uint4*)(hi + o + HID));
        uint4 H2 = __ldcg((const uint4*)(hi + o + 2 * HID));
        uint4 H3 = __ldcg((const uint4*)(hi + o + 3 * HID));
        uint2 M0 = __ldcg((const uint2*)(mi + o));
        uint2 M1 = __ldcg((const uint2*)(mi + o + HID));
        uint2 M2 = __ldcg((const uint2*)(mi + o + 2 * HID));
        uint2 M3 = __ldcg((const uint2*)(mi + o + 3 * HID));
        float4 x0 = sh4[xbase + c * 64];
        float4 x1 = sh4[xbase + c * 64 + 1];
        a0 = fma8(H0, M0, x0, x1, a0);
        a1 = fma8(H1, M1, x0, x1, a1);
        a2 = fma8(H2, M2, x0, x1, a2);
        a3 = fma8(H3, M3, x0, x1, a3);
    }
    #pragma unroll
    for (int off = 16; off; off >>= 1) {
        a0 += __shfl_xor_sync(0xffffffffu, a0, off);
        a1 += __shfl_xor_sync(0xffffffffu, a1, off);
        a2 += __shfl_xor_sync(0xffffffffu, a2, off);
        a3 += __shfl_xor_sync(0xffffffffu, a3, off);
    }
    if (lane == 0) {
        s_d[(rloc    ) * 2 + half] = a0;
        s_d[(rloc + 1) * 2 + half] = a1;
        s_d[(rloc + 2) * 2 + half] = a2;
        s_d[(rloc + 3) * 2 + half] = a3;
    }
}

// ---------------- conversion kernel ----------------
__global__ void conv_kernel(const float* __restrict__ whh0,
                            const float* __restrict__ wih1,
                            const float* __restrict__ whh1) {
    int gid = blockIdx.x * blockDim.x + threadIdx.x;
    for (int i = gid; i < NWEL; i += gridDim.x * blockDim.x) {
        uint32_t u;
        u = __float_as_uint(whh0[i]) + 0x80u;
        g_hi_hh0[i] = (unsigned short)(u >> 16); g_mi_hh0[i] = (unsigned char)(u >> 8);
        u = __float_as_uint(wih1[i]) + 0x80u;
        g_hi_ih1[i] = (unsigned short)(u >> 16); g_mi_ih1[i] = (unsigned char)(u >> 8);
        u = __float_as_uint(whh1[i]) + 0x80u;
        g_hi_hh1[i] = (unsigned short)(u >> 16); g_mi_hh1[i] = (unsigned char)(u >> 8);
    }
    if (gid < STOT) g_keys[gid] = threefry2x32(0u, 42u, 0u, (uint32_t)gid);
}

// ---------------- main persistent kernel ----------------
__global__ void __launch_bounds__(TPB, 1)
lstm_autoreg_kernel(const float* __restrict__ inputs,
                    const float* __restrict__ h_init,
                    const float* __restrict__ c_init,
                    const float* __restrict__ W_ih0,
                    const float* __restrict__ b_ih0,
                    const float* __restrict__ b_hh0,
                    const float* __restrict__ b_ih1,
                    const float* __restrict__ b_hh1,
                    const float* __restrict__ W_lin,
                    const float* __restrict__ b_lin,
                    const float* __restrict__ lookup,
                    float* __restrict__ out)
{
    __shared__ float s_hA[HID];       // h0(s) staging (heavy)
    __shared__ float s_hB[HID];       // h1(s-1) staging (light)
    __shared__ float s_Wih0[RPC][INSZ];
    __shared__ float s_bias0[RPC];
    __shared__ float s_bias1[RPC];
    __shared__ float s_gih0[RPC];
    __shared__ float s_d1[RPC * 2];   // hh0 . h0(s)  (written heavy(s), read light(s+1))
    __shared__ float s_d3[RPC * 2];   // hh1 . h1(s-1)
    __shared__ float s_d2[RPC * 2];   // ih1 . h0(s)
    __shared__ float s_c0[UPC], s_c1[UPC];
    __shared__ float s_x[INSZ];
    __shared__ float s_Wlin[NOUT][UPC];
    __shared__ float s_lookup[NOUT];
    __shared__ float s_blin[NOUT];

    const int tid  = threadIdx.x;
    const int cta  = blockIdx.x;
    const int u0   = cta * UPC;
    const int warp = tid >> 5;
    const int lane = tid & 31;
    const float neginf = __int_as_float(0xff800000);

    // worker geometry (warps 0..23)
    const int half = warp & 1;
    const int rloc = (warp >> 1) * 4;
    const size_t grow = (size_t)((rloc / UPC) * HID + u0 + (rloc % UPC));
    const size_t rowb = grow * HID + half * 768 + lane * 8;
    const int xbase = half * 192 + lane * 2;

    // per-thread barrier epoch (persistent across graph replays via g_epoch_base)
    unsigned epoch;
    asm volatile("ld.relaxed.gpu.u32 %0,[%1];" : "=r"(epoch) : "l"(&g_epoch_base));

    // ---------------- one-time init ----------------
    for (int r = tid; r < RPC; r += TPB) {
        int t = r / UPC, ul = r - t * UPC;
        int g = t * HID + u0 + ul;
        s_bias0[r] = b_ih0[g] + b_hh0[g];
        s_bias1[r] = b_ih1[g] + b_hh1[g];
    }
    for (int idx = tid; idx < RPC * INSZ; idx += TPB) {
        int r = idx >> 5, k = idx & 31;
        int t = r / UPC, ul = r - t * UPC;
        s_Wih0[r][k] = W_ih0[(t * HID + u0 + ul) * INSZ + k];
    }
    for (int idx = tid; idx < NOUT * UPC; idx += TPB) {
        int o = idx / UPC, ul = idx - o * UPC;
        s_Wlin[o][ul] = W_lin[o * HID + u0 + ul];
    }
    if (tid < NOUT) { s_lookup[tid] = lookup[tid]; s_blin[tid] = b_lin[tid]; }
    if (tid < UPC) {
        s_c0[tid] = c_init[u0 + tid];
        s_c1[tid] = c_init[HID + u0 + tid];
        g_h0[u0 + tid] = h_init[u0 + tid];
        g_h1[u0 + tid] = h_init[HID + u0 + tid];
    }
    if (cta == 0 && tid < 2 * NOUT) ((float*)g_logits)[tid] = 0.f;
    grid_barrier(epoch, cta, tid);

    // prologue: stage h0(init); workers compute d1(0) = Whh0 . h0(init)
    if (tid < HV4) ((float4*)s_hA)[tid] = __ldcg(((const float4*)g_h0) + tid);
    __syncthreads();
    if (warp < CTRL)
        dotg1(g_hi_hh0, g_mi_hh0, rowb, (const float4*)s_hA, xbase, lane, half, rloc, s_d1);

    for (int s = 0; s < STOT; ++s) {
        // ================= LIGHT PHASE =================
        if (tid < HV4) ((float4*)s_hB)[tid] = __ldcg(((const float4*)g_h1) + tid);
        __syncthreads();   // hB staged; prior-phase s_d1 writes visible

        if (warp == CTRL) {
            // ---- control: sample(s-1) -> x/gih0 -> cell0, all while workers dot ----
            const int sp = s - 1;
            if (sp >= 0) {
                float logit = neginf;
                if (lane < NOUT) logit = __ldcg(&g_logits[sp & 1][lane]) + s_blin[lane];
                uint2 key = g_keys[sp];
                float v = neginf;
                if (lane < NOUT) {
                    uint2 bb = threefry2x32(key.x, key.y, 0u, (uint32_t)lane);
                    uint32_t bits = bb.x ^ bb.y;
                    float f = __uint_as_float((bits >> 9) | 0x3F800000u) - 1.0f;
                    float u = fmaxf(f + 1.17549435e-38f, 1.17549435e-38f);
                    v = logit - logf(-logf(u));
                }
                int aidx = lane;
                #pragma unroll
                for (int off = 16; off; off >>= 1) {
                    float ov = __shfl_xor_sync(0xffffffffu, v, off);
                    int   oi = __shfl_xor_sync(0xffffffffu, aidx, off);
                    if (ov > v || (ov == v && oi < aidx)) { v = ov; aidx = oi; }
                }
                float m = (lane < NOUT) ? logit : neginf;
                #pragma unroll
                for (int off = 16; off; off >>= 1)
                    m = fmaxf(m, __shfl_xor_sync(0xffffffffu, m, off));
                float e = (lane < NOUT) ? expf(logit - m) : 0.f;
                float sum = e;
                #pragma unroll
                for (int off = 16; off; off >>= 1)
                    sum += __shfl_xor_sync(0xffffffffu, sum, off);

                const int jp = sp & 31;
                if (jp != 0) {
                    float sc = s_lookup[aidx];
                    float xj = s_x[jp];
                    float d  = (sc - 1.0f) * xj;
                    #pragma unroll
                    for (int r = lane; r < RPC; r += 32)
                        s_gih0[r] = fmaf(d, s_Wih0[r][jp], s_gih0[r]);
                    if (lane == 0) s_x[jp] = xj * sc;
                }
                if (cta == 0) {
                    if (lane == 0) out[sp] = (float)aidx;
                    if (lane < NOUT) out[STOT + sp * NOUT + lane] = e / sum;
                }
            }
            if ((s & 31) == 0) {
                s_x[lane] = inputs[(s >> 5) * INSZ + lane];
                __syncwarp();
                for (int r = lane; r < RPC; r += 32) {
                    float acc = s_bias0[r];
                    #pragma unroll
                    for (int k = 0; k < INSZ; ++k)
                        acc = fmaf(s_x[k], s_Wih0[r][k], acc);
                    s_gih0[r] = acc;
                }
            }
            __syncwarp();
            // cell0 (hidden under workers' d3): h0(s) from s_d1 (last heavy) + gih0
            if (lane < UPC) {
                int r0 = lane, r1 = UPC + lane, r2 = 2 * UPC + lane, r3 = 3 * UPC + lane;
                float gi = s_d1[r0*2] + s_d1[r0*2+1] + s_gih0[r0];
                float gf = s_d1[r1*2] + s_d1[r1*2+1] + s_gih0[r1];
                float gg = s_d1[r2*2] + s_d1[r2*2+1] + s_gih0[r2];
                float go = s_d1[r3*2] + s_d1[r3*2+1] + s_gih0[r3];
                float c2 = sigf(gf) * s_c0[lane] + sigf(gi) * tanhf(gg);
                float h2 = sigf(go) * tanhf(c2);
                s_c0[lane] = c2;
                g_h0[u0 + lane] = h2;
            }
        } else {
            // workers: d3 = Whh1 . h1(s-1)
            dotg1(g_hi_hh1, g_mi_hh1, rowb, (const float4*)s_hB,
                  xbase, lane, half, rloc, s_d3);
            if (cta == 0 && warp == 2 && lane < NOUT) g_logits[s & 1][lane] = 0.f;
        }
        grid_barrier(epoch, cta, tid);    // A: h0(s) + d3 + gih0 complete and visible

        // ================= HEAVY PHASE =================
        if (tid < HV4) ((float4*)s_hA)[tid] = __ldcg(((const float4*)g_h0) + tid);
        __syncthreads();   // hA staged

        if (warp < CTRL) {
            // d2 = Wih1 . h0(s)
            dotg1(g_hi_ih1, g_mi_ih1, rowb, (const float4*)s_hA,
                  xbase, lane, half, rloc, s_d2);
        }
        __syncthreads();   // d2 done -> control can run cell1 under workers' d1

        if (warp == CTRL) {
            // cell1 + logits (hidden under workers' d1)
            float h2 = 0.f;
            if (lane < UPC) {
                int r0 = lane, r1 = UPC + lane, r2 = 2 * UPC + lane, r3 = 3 * UPC + lane;
                float gi = s_d2[r0*2] + s_d2[r0*2+1] + s_d3[r0*2] + s_d3[r0*2+1] + s_bias1[r0];
                float gf = s_d2[r1*2] + s_d2[r1*2+1] + s_d3[r1*2] + s_d3[r1*2+1] + s_bias1[r1];
                float gg = s_d2[r2*2] + s_d2[r2*2+1] + s_d3[r2*2] + s_d3[r2*2+1] + s_bias1[r2];
                float go = s_d2[r3*2] + s_d2[r3*2+1] + s_d3[r3*2] + s_d3[r3*2+1] + s_bias1[r3];
                float c2 = sigf(gf) * s_c1[lane] + sigf(gi) * tanhf(gg);
                h2 = sigf(go) * tanhf(c2);
                s_c1[lane] = c2;
                g_h1[u0 + lane] = h2;
            }
            float acc = 0.f;
            #pragma unroll
            for (int ul = 0; ul < UPC; ++ul) {
                float hv = __shfl_sync(0xffffffffu, h2, ul);
                if (lane < NOUT) acc = fmaf(hv, s_Wlin[lane][ul], acc);
            }
            if (lane < NOUT) atomicAdd(&g_logits[s & 1][lane], acc);
        } else {
            // d1(s+1) = Whh0 . h0(s)
            dotg1(g_hi_hh0, g_mi_hh0, rowb, (const float4*)s_hA,
                  xbase, lane, half, rloc, s_d1);
        }
        grid_barrier(epoch, cta, tid);    // B: h1(s), logits, d1(s+1) complete and visible
    }

    // persist epoch for the next launch (graph replays)
    if (cta == 0 && tid == 0)
        asm volatile("st.relaxed.gpu.u32 [%0],%1;" :: "l"(&g_epoch_base), "r"(epoch));

    // ---- epilogue: sample the final step (cta 0 only) ----
    if (cta == 0 && warp == CTRL) {
        const int sp = STOT - 1;
        float logit = neginf;
        if (lane < NOUT) logit = __ldcg(&g_logits[sp & 1][lane]) + s_blin[lane];
        uint2 key = g_keys[sp];
        float v = neginf;
        if (lane < NOUT) {
            uint2 bb = threefry2x32(key.x, key.y, 0u, (uint32_t)lane);
            uint32_t bits = bb.x ^ bb.y;
            float f = __uint_as_float((bits >> 9) | 0x3F800000u) - 1.0f;
            float u = fmaxf(f + 1.17549435e-38f, 1.17549435e-38f);
            v = logit - logf(-logf(u));
        }
        int aidx = lane;
        #pragma unroll
        for (int off = 16; off; off >>= 1) {
            float ov = __shfl_xor_sync(0xffffffffu, v, off);
            int   oi = __shfl_xor_sync(0xffffffffu, aidx, off);
            if (ov > v || (ov == v && oi < aidx)) { v = ov; aidx = oi; }
        }
        float m = (lane < NOUT) ? logit : neginf;
        #pragma unroll
        for (int off = 16; off; off >>= 1)
            m = fmaxf(m, __shfl_xor_sync(0xffffffffu, m, off));
        float e = (lane < NOUT) ? expf(logit - m) : 0.f;
        float sum = e;
        #pragma unroll
        for (int off = 16; off; off >>= 1)
            sum += __shfl_xor_sync(0xffffffffu, sum, off);
        if (lane == 0) out[sp] = (float)aidx;
        if (lane < NOUT) out[STOT + sp * NOUT + lane] = e / sum;
    }
}

extern "C" void kernel_launch(void* const* d_in, const int* in_sizes, int n_in,
                              void* d_out, int out_size) {
    (void)in_sizes; (void)n_in; (void)out_size;
    conv_kernel<<<4608, 1024>>>(
        (const float*)d_in[4],   // W_hh0
        (const float*)d_in[7],   // W_ih1
        (const float*)d_in[8]);  // W_hh1
    lstm_autoreg_kernel<<<NCTA, TPB>>>(
        (const float*)d_in[0],   // inputs
        (const float*)d_in[1],   // h_init
        (const float*)d_in[2],   // c_init
        (const float*)d_in[3],   // W_ih0
        (const float*)d_in[5],   // b_ih0
        (const float*)d_in[6],   // b_hh0
        (const float*)d_in[9],   // b_ih1
        (const float*)d_in[10],  // b_hh1
        (const float*)d_in[11],  // W_lin
        (const float*)d_in[12],  // b_lin
        (const float*)d_in[13],  // lookup
        (float*)d_out);
}

// round 17
// speedup vs baseline: 1.1458x; 1.1458x over previous
#include <cuda_runtime.h>
#include <math.h>
#include <stdint.h>

#define NCTA  128
#define TPB   800             // warps 0..23 = dot workers, warp 24 = control
#define HID   1536
#define INSZ  32
#define NOUT  10
#define STOT  2048
#define UPC   12              // hidden units per CTA
#define RPC   48              // gate rows per CTA
#define HV4   (HID / 4)
#define NWEL  (4 * HID * HID)
#define CTRL  24              // control warp id

// ---------------- persistent device state ----------------
__device__ unsigned short g_hi_hh0[NWEL];
__device__ unsigned short g_hi_ih1[NWEL];
__device__ unsigned short g_hi_hh1[NWEL];
__device__ unsigned char  g_mi_hh0[NWEL];
__device__ unsigned char  g_mi_ih1[NWEL];
__device__ unsigned char  g_mi_hh1[NWEL];

__device__ __align__(16) float g_h0[HID];
__device__ __align__(16) float g_h1[HID];
__device__ float    g_logits[2][NOUT];
__device__ uint2    g_keys[STOT];
__device__ unsigned g_bar_count = 0;
__device__ unsigned g_bar_gen   = 0;

// ---------------- grid barrier (acq_rel atomics — best mechanism tested) ----------------
__device__ __forceinline__ void grid_barrier() {
    __syncthreads();
    if (threadIdx.x == 0) {
        unsigned g;
        asm volatile("ld.relaxed.gpu.u32 %0,[%1];" : "=r"(g) : "l"(&g_bar_gen));
        unsigned arrived;
        asm volatile("atom.acq_rel.gpu.add.u32 %0,[%1],1;"
                     : "=r"(arrived) : "l"(&g_bar_count));
        if (arrived == NCTA - 1) {
            asm volatile("st.relaxed.gpu.u32 [%0],%1;" :: "l"(&g_bar_count), "r"(0u));
            asm volatile("st.release.gpu.u32 [%0],%1;" :: "l"(&g_bar_gen), "r"(g + 1u));
        } else {
            unsigned cur;
            do {
                asm volatile("ld.acquire.gpu.u32 %0,[%1];" : "=r"(cur) : "l"(&g_bar_gen));
            } while (cur == g);
        }
    }
    __syncthreads();
}

// ---------------- JAX threefry2x32 ----------------
__device__ __forceinline__ void tf_round(uint32_t& x0, uint32_t& x1, int r) {
    x0 += x1;
    x1 = (x1 << r) | (x1 >> (32 - r));
    x1 ^= x0;
}
__device__ __forceinline__ uint2 threefry2x32(uint32_t k0, uint32_t k1,
                                              uint32_t x0, uint32_t x1) {
    uint32_t ks2 = k0 ^ k1 ^ 0x1BD11BDAu;
    x0 += k0; x1 += k1;
    tf_round(x0,x1,13); tf_round(x0,x1,15); tf_round(x0,x1,26); tf_round(x0,x1,6);
    x0 += k1; x1 += ks2 + 1u;
    tf_round(x0,x1,17); tf_round(x0,x1,29); tf_round(x0,x1,16); tf_round(x0,x1,24);
    x0 += ks2; x1 += k0 + 2u;
    tf_round(x0,x1,13); tf_round(x0,x1,15); tf_round(x0,x1,26); tf_round(x0,x1,6);
    x0 += k0; x1 += k1 + 3u;
    tf_round(x0,x1,17); tf_round(x0,x1,29); tf_round(x0,x1,16); tf_round(x0,x1,24);
    x0 += k1; x1 += ks2 + 4u;
    tf_round(x0,x1,13); tf_round(x0,x1,15); tf_round(x0,x1,26); tf_round(x0,x1,6);
    x0 += ks2; x1 += k0 + 5u;
    return make_uint2(x0, x1);
}

__device__ __forceinline__ float sigf(float x) { return 1.0f / (1.0f + expf(-x)); }

__device__ __forceinline__ float prmtf(uint32_t a, uint32_t b, uint32_t s) {
    uint32_t r;
    asm("prmt.b32 %0,%1,%2,%3;" : "=r"(r) : "r"(a), "r"(b), "r"(s));
    return __uint_as_float(r);
}

__device__ __forceinline__ float fma8(uint4 H, uint2 M, float4 x0, float4 x1, float acc) {
    acc = fmaf(prmtf(H.x, M.x, 0x1044u), x0.x, acc);
    acc = fmaf(prmtf(H.x, M.x, 0x3255u), x0.y, acc);
    acc = fmaf(prmtf(H.y, M.x, 0x1066u), x0.z, acc);
    acc = fmaf(prmtf(H.y, M.x, 0x3277u), x0.w, acc);
    acc = fmaf(prmtf(H.z, M.y, 0x1044u), x1.x, acc);
    acc = fmaf(prmtf(H.z, M.y, 0x3255u), x1.y, acc);
    acc = fmaf(prmtf(H.w, M.y, 0x1066u), x1.z, acc);
    acc = fmaf(prmtf(H.w, M.y, 0x3277u), x1.w, acc);
    return acc;
}

// half-row dot: 4 consecutive rows, one half, x from SMEM (proven engine)
__device__ __forceinline__ void dotg1(const unsigned short* __restrict__ hi,
                                      const unsigned char*  __restrict__ mi,
                                      size_t rowb,
                                      const float4* __restrict__ sh4,
                                      int xbase, int lane, int half, int rloc,
                                      float* __restrict__ s_d) {
    float a0 = 0.f, a1 = 0.f, a2 = 0.f, a3 = 0.f;
    #pragma unroll
    for (int c = 0; c < 3; ++c) {
        const size_t o = rowb + (size_t)c * 256;
        uint4 H0 = __ldcg((const uint4*)(hi + o));
        uint4 H1 = __ldcg((const uint4*)(hi + o + HID));
        uint4 H2 = __ldcg((const uint4*)(hi + o + 2 * HID));
        uint4 H3 = __ldcg((const uint4*)(hi + o + 3 * HID));
        uint2 M0 = __ldcg((const uint2*)(mi + o));
        uint2 M1 = __ldcg((const uint2*)(mi + o + HID));
        uint2 M2 = __ldcg((const uint2*)(mi + o + 2 * HID));
        uint2 M3 = __ldcg((const uint2*)(mi + o + 3 * HID));
        float4 x0 = sh4[xbase + c * 64];
        float4 x1 = sh4[xbase + c * 64 + 1];
        a0 = fma8(H0, M0, x0, x1, a0);
        a1 = fma8(H1, M1, x0, x1, a1);
        a2 = fma8(H2, M2, x0, x1, a2);
        a3 = fma8(H3, M3, x0, x1, a3);
    }
    #pragma unroll
    for (int off = 16; off; off >>= 1) {
        a0 += __shfl_xor_sync(0xffffffffu, a0, off);
        a1 += __shfl_xor_sync(0xffffffffu, a1, off);
        a2 += __shfl_xor_sync(0xffffffffu, a2, off);
        a3 += __shfl_xor_sync(0xffffffffu, a3, off);
    }
    if (lane == 0) {
        s_d[(rloc    ) * 2 + half] = a0;
        s_d[(rloc + 1) * 2 + half] = a1;
        s_d[(rloc + 2) * 2 + half] = a2;
        s_d[(rloc + 3) * 2 + half] = a3;
    }
}

// ---------------- conversion kernel ----------------
__global__ void conv_kernel(const float* __restrict__ whh0,
                            const float* __restrict__ wih1,
                            const float* __restrict__ whh1) {
    int gid = blockIdx.x * blockDim.x + threadIdx.x;
    for (int i = gid; i < NWEL; i += gridDim.x * blockDim.x) {
        uint32_t u;
        u = __float_as_uint(whh0[i]) + 0x80u;
        g_hi_hh0[i] = (unsigned short)(u >> 16); g_mi_hh0[i] = (unsigned char)(u >> 8);
        u = __float_as_uint(wih1[i]) + 0x80u;
        g_hi_ih1[i] = (unsigned short)(u >> 16); g_mi_ih1[i] = (unsigned char)(u >> 8);
        u = __float_as_uint(whh1[i]) + 0x80u;
        g_hi_hh1[i] = (unsigned short)(u >> 16); g_mi_hh1[i] = (unsigned char)(u >> 8);
    }
    if (gid < STOT) g_keys[gid] = threefry2x32(0u, 42u, 0u, (uint32_t)gid);
}

// ---------------- main persistent kernel ----------------
__global__ void __launch_bounds__(TPB, 1)
lstm_autoreg_kernel(const float* __restrict__ inputs,
                    const float* __restrict__ h_init,
                    const float* __restrict__ c_init,
                    const float* __restrict__ W_ih0,
                    const float* __restrict__ b_ih0,
                    const float* __restrict__ b_hh0,
                    const float* __restrict__ b_ih1,
                    const float* __restrict__ b_hh1,
                    const float* __restrict__ W_lin,
                    const float* __restrict__ b_lin,
                    const float* __restrict__ lookup,
                    float* __restrict__ out)
{
    __shared__ float s_hA[HID];       // h0(s) staging (heavy)
    __shared__ float s_hB[HID];       // h1(s-1) staging (light)
    __shared__ float s_Wih0[RPC][INSZ];
    __shared__ float s_bias0[RPC];
    __shared__ float s_bias1[RPC];
    __shared__ float s_gih0[RPC];
    __shared__ float s_d1[RPC * 2];   // hh0 . h0(s)  (written heavy(s), read light(s+1))
    __shared__ float s_d3[RPC * 2];   // hh1 . h1(s-1)
    __shared__ float s_d2[RPC * 2];   // ih1 . h0(s)
    __shared__ float s_c0[UPC], s_c1[UPC];
    __shared__ float s_x[INSZ];
    __shared__ float s_Wlin[NOUT][UPC];
    __shared__ float s_lookup[NOUT];
    __shared__ float s_blin[NOUT];

    const int tid  = threadIdx.x;
    const int cta  = blockIdx.x;
    const int u0   = cta * UPC;
    const int warp = tid >> 5;
    const int lane = tid & 31;
    const float neginf = __int_as_float(0xff800000);

    // worker geometry (warps 0..23)
    const int half = warp & 1;
    const int rloc = (warp >> 1) * 4;
    const size_t grow = (size_t)((rloc / UPC) * HID + u0 + (rloc % UPC));
    const size_t rowb = grow * HID + half * 768 + lane * 8;
    const int xbase = half * 192 + lane * 2;

    // ---------------- one-time init ----------------
    for (int r = tid; r < RPC; r += TPB) {
        int t = r / UPC, ul = r - t * UPC;
        int g = t * HID + u0 + ul;
        s_bias0[r] = b_ih0[g] + b_hh0[g];
        s_bias1[r] = b_ih1[g] + b_hh1[g];
    }
    for (int idx = tid; idx < RPC * INSZ; idx += TPB) {
        int r = idx >> 5, k = idx & 31;
        int t = r / UPC, ul = r - t * UPC;
        s_Wih0[r][k] = W_ih0[(t * HID + u0 + ul) * INSZ + k];
    }
    for (int idx = tid; idx < NOUT * UPC; idx += TPB) {
        int o = idx / UPC, ul = idx - o * UPC;
        s_Wlin[o][ul] = W_lin[o * HID + u0 + ul];
    }
    if (tid < NOUT) { s_lookup[tid] = lookup[tid]; s_blin[tid] = b_lin[tid]; }
    if (tid < UPC) {
        s_c0[tid] = c_init[u0 + tid];
        s_c1[tid] = c_init[HID + u0 + tid];
        g_h0[u0 + tid] = h_init[u0 + tid];
        g_h1[u0 + tid] = h_init[HID + u0 + tid];
    }
    if (cta == 0 && tid < 2 * NOUT) ((float*)g_logits)[tid] = 0.f;
    grid_barrier();

    // prologue: stage h0(init); workers compute d1(0) = Whh0 . h0(init)
    if (tid < HV4) ((float4*)s_hA)[tid] = __ldcg(((const float4*)g_h0) + tid);
    __syncthreads();
    if (warp < CTRL)
        dotg1(g_hi_hh0, g_mi_hh0, rowb, (const float4*)s_hA, xbase, lane, half, rloc, s_d1);

    for (int s = 0; s < STOT; ++s) {
        // ================= LIGHT PHASE =================
        if (tid < HV4) ((float4*)s_hB)[tid] = __ldcg(((const float4*)g_h1) + tid);
        __syncthreads();   // hB staged; prior-phase s_d1 writes visible

        if (warp == CTRL) {
            // ---- control: sample(s-1) -> x/gih0 -> cell0, all while workers dot ----
            const int sp = s - 1;
            if (sp >= 0) {
                float logit = neginf;
                if (lane < NOUT) logit = __ldcg(&g_logits[sp & 1][lane]) + s_blin[lane];
                uint2 key = g_keys[sp];
                float v = neginf;
                if (lane < NOUT) {
                    uint2 bb = threefry2x32(key.x, key.y, 0u, (uint32_t)lane);
                    uint32_t bits = bb.x ^ bb.y;
                    float f = __uint_as_float((bits >> 9) | 0x3F800000u) - 1.0f;
                    float u = fmaxf(f + 1.17549435e-38f, 1.17549435e-38f);
                    v = logit - logf(-logf(u));
                }
                int aidx = lane;
                #pragma unroll
                for (int off = 16; off; off >>= 1) {
                    float ov = __shfl_xor_sync(0xffffffffu, v, off);
                    int   oi = __shfl_xor_sync(0xffffffffu, aidx, off);
                    if (ov > v || (ov == v && oi < aidx)) { v = ov; aidx = oi; }
                }
                float m = (lane < NOUT) ? logit : neginf;
                #pragma unroll
                for (int off = 16; off; off >>= 1)
                    m = fmaxf(m, __shfl_xor_sync(0xffffffffu, m, off));
                float e = (lane < NOUT) ? expf(logit - m) : 0.f;
                float sum = e;
                #pragma unroll
                for (int off = 16; off; off >>= 1)
                    sum += __shfl_xor_sync(0xffffffffu, sum, off);

                const int jp = sp & 31;
                if (jp != 0) {
                    float sc = s_lookup[aidx];
                    float xj = s_x[jp];
                    float d  = (sc - 1.0f) * xj;
                    #pragma unroll
                    for (int r = lane; r < RPC; r += 32)
                        s_gih0[r] = fmaf(d, s_Wih0[r][jp], s_gih0[r]);
                    if (lane == 0) s_x[jp] = xj * sc;
                }
                if (cta == 0) {
                    if (lane == 0) out[sp] = (float)aidx;
                    if (lane < NOUT) out[STOT + sp * NOUT + lane] = e / sum;
                }
            }
            if ((s & 31) == 0) {
                s_x[lane] = inputs[(s >> 5) * INSZ + lane];
                __syncwarp();
                for (int r = lane; r < RPC; r += 32) {
                    float acc = s_bias0[r];
                    #pragma unroll
                    for (int k = 0; k < INSZ; ++k)
                        acc = fmaf(s_x[k], s_Wih0[r][k], acc);
                    s_gih0[r] = acc;
                }
            }
            __syncwarp();
            // cell0 (hidden under workers' d3): h0(s) from s_d1 (last heavy) + gih0
            if (lane < UPC) {
                int r0 = lane, r1 = UPC + lane, r2 = 2 * UPC + lane, r3 = 3 * UPC + lane;
                float gi = s_d1[r0*2] + s_d1[r0*2+1] + s_gih0[r0];
                float gf = s_d1[r1*2] + s_d1[r1*2+1] + s_gih0[r1];
                float gg = s_d1[r2*2] + s_d1[r2*2+1] + s_gih0[r2];
                float go = s_d1[r3*2] + s_d1[r3*2+1] + s_gih0[r3];
                float c2 = sigf(gf) * s_c0[lane] + sigf(gi) * tanhf(gg);
                float h2 = sigf(go) * tanhf(c2);
                s_c0[lane] = c2;
                g_h0[u0 + lane] = h2;
            }
        } else {
            // workers: d3 = Whh1 . h1(s-1)
            dotg1(g_hi_hh1, g_mi_hh1, rowb, (const float4*)s_hB,
                  xbase, lane, half, rloc, s_d3);
            if (cta == 0 && warp == 2 && lane < NOUT) g_logits[s & 1][lane] = 0.f;
        }
        grid_barrier();    // A: h0(s) + d3 + gih0 complete and visible

        // ================= HEAVY PHASE =================
        if (tid < HV4) ((float4*)s_hA)[tid] = __ldcg(((const float4*)g_h0) + tid);
        __syncthreads();   // hA staged

        if (warp < CTRL) {
            // d2 = Wih1 . h0(s); hand off to control via named barrier, then
            // flow straight into d1 (no block-wide sync)
            dotg1(g_hi_ih1, g_mi_ih1, rowb, (const float4*)s_hA,
                  xbase, lane, half, rloc, s_d2);
            asm volatile("bar.arrive 1, %0;" :: "n"(TPB) : "memory");
            // d1(s+1) = Whh0 . h0(s)
            dotg1(g_hi_hh0, g_mi_hh0, rowb, (const float4*)s_hA,
                  xbase, lane, half, rloc, s_d1);
        } else {
            // control: wait for d2 producers, then cell1 + logits (|| workers' d1)
            asm volatile("bar.sync 1, %0;" :: "n"(TPB) : "memory");
            float h2 = 0.f;
            if (lane < UPC) {
                int r0 = lane, r1 = UPC + lane, r2 = 2 * UPC + lane, r3 = 3 * UPC + lane;
                float gi = s_d2[r0*2] + s_d2[r0*2+1] + s_d3[r0*2] + s_d3[r0*2+1] + s_bias1[r0];
                float gf = s_d2[r1*2] + s_d2[r1*2+1] + s_d3[r1*2] + s_d3[r1*2+1] + s_bias1[r1];
                float gg = s_d2[r2*2] + s_d2[r2*2+1] + s_d3[r2*2] + s_d3[r2*2+1] + s_bias1[r2];
                float go = s_d2[r3*2] + s_d2[r3*2+1] + s_d3[r3*2] + s_d3[r3*2+1] + s_bias1[r3];
                float c2 = sigf(gf) * s_c1[lane] + sigf(gi) * tanhf(gg);
                h2 = sigf(go) * tanhf(c2);
                s_c1[lane] = c2;
                g_h1[u0 + lane] = h2;
            }
            float acc = 0.f;
            #pragma unroll
            for (int ul = 0; ul < UPC; ++ul) {
                float hv = __shfl_sync(0xffffffffu, h2, ul);
                if (lane < NOUT) acc = fmaf(hv, s_Wlin[lane][ul], acc);
            }
            if (lane < NOUT) atomicAdd(&g_logits[s & 1][lane], acc);
        }
        grid_barrier();    // B: h1(s), logits, d1(s+1) complete and visible
    }

    // ---- epilogue: sample the final step (cta 0 only) ----
    if (cta == 0 && warp == CTRL) {
        const int sp = STOT - 1;
        float logit = neginf;
        if (lane < NOUT) logit = __ldcg(&g_logits[sp & 1][lane]) + s_blin[lane];
        uint2 key = g_keys[sp];
        float v = neginf;
        if (lane < NOUT) {
            uint2 bb = threefry2x32(key.x, key.y, 0u, (uint32_t)lane);
            uint32_t bits = bb.x ^ bb.y;
            float f = __uint_as_float((bits >> 9) | 0x3F800000u) - 1.0f;
            float u = fmaxf(f + 1.17549435e-38f, 1.17549435e-38f);
            v = logit - logf(-logf(u));
        }
        int aidx = lane;
        #pragma unroll
        for (int off = 16; off; off >>= 1) {
            float ov = __shfl_xor_sync(0xffffffffu, v, off);
            int   oi = __shfl_xor_sync(0xffffffffu, aidx, off);
            if (ov > v || (ov == v && oi < aidx)) { v = ov; aidx = oi; }
        }
        float m = (lane < NOUT) ? logit : neginf;
        #pragma unroll
        for (int off = 16; off; off >>= 1)
            m = fmaxf(m, __shfl_xor_sync(0xffffffffu, m, off));
        float e = (lane < NOUT) ? expf(logit - m) : 0.f;
        float sum = e;
        #pragma unroll
        for (int off = 16; off; off >>= 1)
            sum += __shfl_xor_sync(0xffffffffu, sum, off);
        if (lane == 0) out[sp] = (float)aidx;
        if (lane < NOUT) out[STOT + sp * NOUT + lane] = e / sum;
    }
}

extern "C" void kernel_launch(void* const* d_in, const int* in_sizes, int n_in,
                              void* d_out, int out_size) {
    (void)in_sizes; (void)n_in; (void)out_size;
    conv_kernel<<<4608, 1024>>>(
        (const float*)d_in[4],   // W_hh0
        (const float*)d_in[7],   // W_ih1
        (const float*)d_in[8]);  // W_hh1
    lstm_autoreg_kernel<<<NCTA, TPB>>>(
        (const float*)d_in[0],   // inputs
        (const float*)d_in[1],   // h_init
        (const float*)d_in[2],   // c_init
        (const float*)d_in[3],   // W_ih0
        (const float*)d_in[5],   // b_ih0
        (const float*)d_in[6],   // b_hh0
        (const float*)d_in[9],   // b_ih1
        (const float*)d_in[10],  // b_hh1
        (const float*)d_in[11],  // W_lin
        (const float*)d_in[12],  // b_lin
        (const float*)d_in[13],  // lookup
        (float*)d_out);
}